// round 14
// baseline (speedup 1.0000x reference)
#include <cuda_runtime.h>
#include <cuda_fp16.h>
#include <math.h>
#include <stdint.h>

// ---------------------------------------------------------------------------
// Problem constants
// ---------------------------------------------------------------------------
namespace {
constexpr int Bk = 4;       // batch
constexpr int Tk = 1024;    // seq len
constexpr int INk = 256;    // input dim
constexpr int Dk = 1024;    // model dim
constexpr int Hk = 16;      // heads
constexpr int HDk = 64;     // head dim
constexpr int FFk = 4096;   // ff dim
constexpr int Ck = 10;      // classes
constexpr int Lk = 6;       // layers
constexpr int D3k = 3 * Dk;
constexpr float EPSk = 1e-5f;
}

// ---------------------------------------------------------------------------
// Scratch buffers (static device globals — no allocations allowed)
// ---------------------------------------------------------------------------
__device__ float g_h[Bk * Tk * Dk];
__device__ float g_tmp[Bk * Tk * Dk];

// single fp16 activation buffers
__device__ __half g_x_h[Bk * Tk * INk];
__device__ __half g_h_h[Bk * Tk * Dk];
__device__ __half g_o_h[Bk * Tk * Dk];
__device__ __half g_ff_h[Bk * Tk * FFk];
// qkv kept hi/lo (feeds 3-term flash attention)
__device__ __half g_qkv_hi[Bk * Tk * D3k], g_qkv_lo[Bk * Tk * D3k];

// fp16 weight buffers (single rounding)
__device__ __half g_win_h[Dk * INk];
__device__ __half g_wqkv_h[Lk * D3k * Dk];
__device__ __half g_wo_h[Lk * Dk * Dk];
__device__ __half g_w1_h[Lk * FFk * Dk];
__device__ __half g_w2_h[Lk * Dk * FFk];

// ---------------------------------------------------------------------------
// PTX helpers (sm_80-era features only — compile on base sm_100)
// ---------------------------------------------------------------------------
__device__ __forceinline__ uint32_t smem_u32(const void* p) {
    uint32_t a;
    asm("{ .reg .u64 t; cvta.to.shared.u64 t, %1; cvt.u32.u64 %0, t; }"
        : "=r"(a) : "l"(p));
    return a;
}

__device__ __forceinline__ void ldmat_x4(uint32_t* r, uint32_t addr) {
    asm volatile("ldmatrix.sync.aligned.m8n8.x4.shared.b16 {%0,%1,%2,%3}, [%4];"
                 : "=r"(r[0]), "=r"(r[1]), "=r"(r[2]), "=r"(r[3]) : "r"(addr));
}

__device__ __forceinline__ void ldmat_x4_t(uint32_t* r, uint32_t addr) {
    asm volatile("ldmatrix.sync.aligned.m8n8.x4.trans.shared.b16 {%0,%1,%2,%3}, [%4];"
                 : "=r"(r[0]), "=r"(r[1]), "=r"(r[2]), "=r"(r[3]) : "r"(addr));
}

// fp16 mma
__device__ __forceinline__ void mma16816h(float* c, const uint32_t* a,
                                          uint32_t b0, uint32_t b1) {
    asm volatile(
        "mma.sync.aligned.m16n8k16.row.col.f32.f16.f16.f32 "
        "{%0,%1,%2,%3}, {%4,%5,%6,%7}, {%8,%9}, {%0,%1,%2,%3};"
        : "+f"(c[0]), "+f"(c[1]), "+f"(c[2]), "+f"(c[3])
        : "r"(a[0]), "r"(a[1]), "r"(a[2]), "r"(a[3]), "r"(b0), "r"(b1));
}

__device__ __forceinline__ void sts128(uint32_t addr, uint4 v) {
    asm volatile("st.shared.v4.b32 [%0], {%1,%2,%3,%4};"
                 :: "r"(addr), "r"(v.x), "r"(v.y), "r"(v.z), "r"(v.w) : "memory");
}

__device__ __forceinline__ void cp_async16(uint32_t saddr, const void* gptr) {
    asm volatile("cp.async.cg.shared.global [%0], [%1], 16;"
                 :: "r"(saddr), "l"(gptr) : "memory");
}
#define CP_COMMIT() asm volatile("cp.async.commit_group;" ::: "memory")
#define CP_WAIT1()  asm volatile("cp.async.wait_group 1;" ::: "memory")
#define CP_WAIT0()  asm volatile("cp.async.wait_group 0;" ::: "memory")

// ---- fp16 hi/lo split
__device__ __forceinline__ void cvt_hilo2h(float a, float b, uint32_t& hi, uint32_t& lo) {
    __half2 h = __floats2half2_rn(a, b);
    float2 hf = __half22float2(h);
    __half2 l = __floats2half2_rn(a - hf.x, b - hf.y);
    hi = *reinterpret_cast<uint32_t*>(&h);
    lo = *reinterpret_cast<uint32_t*>(&l);
}

__device__ __forceinline__ uint32_t cvt_h2(float a, float b) {
    __half2 h = __floats2half2_rn(a, b);
    return *reinterpret_cast<uint32_t*>(&h);
}

// ---------------------------------------------------------------------------
// Conversion kernel (fp32 -> fp16)
// ---------------------------------------------------------------------------
__global__ __launch_bounds__(256) void cvt_h16_kernel(
    const float* __restrict__ src, __half* __restrict__ dst, int n)
{
    const int i = (blockIdx.x * 256 + threadIdx.x) * 4;
    if (i >= n) return;
    float4 v = *(const float4*)(src + i);
    *(uint2*)(dst + i) = make_uint2(cvt_h2(v.x, v.y), cvt_h2(v.z, v.w));
}

// ---------------------------------------------------------------------------
// fp16 single-term NT GEMM: C = A * W^T + bias.
// 256x128 block tile, 8 warps (4m x 2n), warp tile 64x64.
// BK=32, 3-stage cp.async pipeline. 1 CTA/SM (fat registers).
// flags: 1=relu, 2=write fp32 C, 4=write fp16 hi/lo C, 8=write fp16 C
// ---------------------------------------------------------------------------
namespace {
constexpr int SST = 40;                         // smem row stride (fp16)
constexpr int ARR_A = 256 * SST * 2;            // 20480 bytes (A tile)
constexpr int ARR_BB = 128 * SST * 2;           // 10240 bytes (B tile)
constexpr int STAGE_B = ARR_A + ARR_BB;         // 30720 bytes per stage
}
static constexpr int GEMM_SMEM = 3 * STAGE_B;   // 92160

__global__ __launch_bounds__(256) void mma_gemm_f16_nt(
    const __half* __restrict__ Ah, int lda,
    const __half* __restrict__ Bh, int ldb,
    const float* __restrict__ bias,
    float* __restrict__ Cf, __half* __restrict__ Chi, __half* __restrict__ Clo,
    int ldc, int K, int flags)
{
    extern __shared__ __align__(16) char gsm[];
    const uint32_t base = smem_u32(gsm);

    const int tid  = threadIdx.x;
    const int lane = tid & 31;
    const int wid  = tid >> 5;
    const int wm   = wid & 3;        // 4 m-warps x 64 rows
    const int wn   = wid >> 2;       // 2 n-warps x 64 cols
    const int row0 = blockIdx.y * 256;
    const int col0 = blockIdx.x * 128;

    // global loads: A: thread -> full row (32 fp16) of 256-row tile
    //               B: thread -> half row (16 fp16) of 128-row tile
    const __half* Ah_p = Ah + (size_t)(row0 + tid) * lda;
    const int brow = tid >> 1;
    const int bc16 = (tid & 1) * 16;
    const __half* Bh_p = Bh + (size_t)(col0 + brow) * ldb + bc16;
    const uint32_t soffA = tid * (SST * 2);
    const uint32_t soffB = brow * (SST * 2) + bc16 * 2;

    const uint32_t aRowOff = (uint32_t)((wm * 64 + (lane & 15)) * SST * 2 + (lane >> 4) * 16);
    const uint32_t bRowOff = (uint32_t)(((wn * 64 + ((lane >> 4) << 3) + (lane & 7)) * SST) * 2
                                        + ((lane >> 3) & 1) * 16);

    float acc[4][8][4];
#pragma unroll
    for (int i = 0; i < 4; i++)
#pragma unroll
        for (int j = 0; j < 8; j++)
#pragma unroll
            for (int q = 0; q < 4; q++) acc[i][j][q] = 0.f;

    const int nc = K >> 5;

    auto issue = [&](int c, int s) {
        const uint32_t sb = base + s * STAGE_B;
        const __half* p = Ah_p + c * 32;
        cp_async16(sb + soffA, p);
        cp_async16(sb + soffA + 16, p + 8);
        cp_async16(sb + soffA + 32, p + 16);
        cp_async16(sb + soffA + 48, p + 24);
        p = Bh_p + c * 32;
        cp_async16(sb + ARR_A + soffB, p);
        cp_async16(sb + ARR_A + soffB + 16, p + 8);
        CP_COMMIT();
    };

    issue(0, 0);
    if (nc > 1) issue(1, 1);

    for (int c = 0; c < nc; c++) {
        if (c + 1 < nc) { CP_WAIT1(); }
        else            { CP_WAIT0(); }
        __syncthreads();
        if (c + 2 < nc) issue(c + 2, (c + 2) % 3);

        const uint32_t sb = base + (c % 3) * STAGE_B;
        const uint32_t aS = sb, bS = sb + ARR_A;

#pragma unroll
        for (int ks = 0; ks < 2; ks++) {
            const uint32_t kb = ks * 32;
            uint32_t A4[4][4];
#pragma unroll
            for (int mt = 0; mt < 4; mt++)
                ldmat_x4(A4[mt], aS + aRowOff + mt * (16 * SST * 2) + kb);
#pragma unroll
            for (int pr = 0; pr < 4; pr++) {
                uint32_t B4[4];
                ldmat_x4(B4, bS + bRowOff + pr * (16 * SST * 2) + kb);
#pragma unroll
                for (int sbb = 0; sbb < 2; sbb++) {
                    const int nt = pr * 2 + sbb;
#pragma unroll
                    for (int mt = 0; mt < 4; mt++)
                        mma16816h(acc[mt][nt], A4[mt], B4[sbb * 2], B4[sbb * 2 + 1]);
                }
            }
        }
    }
    __syncthreads();

    // ---- epilogue
    const int erow = lane >> 2;
    const int ecol = (lane & 3) * 2;
    const int relu = flags & 1;
#pragma unroll
    for (int mt = 0; mt < 4; mt++) {
        const int r = row0 + wm * 64 + mt * 16 + erow;
#pragma unroll
        for (int nt = 0; nt < 8; nt++) {
            const int cc = col0 + wn * 64 + nt * 8 + ecol;
            float2 bv = *(const float2*)(bias + cc);
            float2 v0, v1;
            v0.x = acc[mt][nt][0] + bv.x;  v0.y = acc[mt][nt][1] + bv.y;
            v1.x = acc[mt][nt][2] + bv.x;  v1.y = acc[mt][nt][3] + bv.y;
            if (relu) {
                v0.x = fmaxf(v0.x, 0.f); v0.y = fmaxf(v0.y, 0.f);
                v1.x = fmaxf(v1.x, 0.f); v1.y = fmaxf(v1.y, 0.f);
            }
            if (flags & 2) {
                *(float2*)(Cf + (size_t)r * ldc + cc)       = v0;
                *(float2*)(Cf + (size_t)(r + 8) * ldc + cc) = v1;
            }
            if (flags & 4) {
                uint32_t hv, lv;
                cvt_hilo2h(v0.x, v0.y, hv, lv);
                *(uint32_t*)(Chi + (size_t)r * ldc + cc) = hv;
                *(uint32_t*)(Clo + (size_t)r * ldc + cc) = lv;
                cvt_hilo2h(v1.x, v1.y, hv, lv);
                *(uint32_t*)(Chi + (size_t)(r + 8) * ldc + cc) = hv;
                *(uint32_t*)(Clo + (size_t)(r + 8) * ldc + cc) = lv;
            }
            if (flags & 8) {
                *(uint32_t*)(Chi + (size_t)r * ldc + cc)       = cvt_h2(v0.x, v0.y);
                *(uint32_t*)(Chi + (size_t)(r + 8) * ldc + cc) = cvt_h2(v1.x, v1.y);
            }
        }
    }
}

// ---------------------------------------------------------------------------
// Fused flash attention on pre-split fp16 hi/lo qkv (3-term fp16 MMAs).
// K/V via cp.async 3-stage ring. Output: single fp16 o.
// ---------------------------------------------------------------------------
namespace {
constexpr int KST   = 72;                 // smem row stride (fp16)
constexpr int ARR_F = 128 * KST * 2;      // 18432 bytes per array
constexpr int STAGE_F = 4 * ARR_F;        // Khi|Klo|Vhi|Vlo = 73728
}
static constexpr int FLASH_SMEM = 3 * STAGE_F;   // 221184

__global__ __launch_bounds__(256) void flash_attn_kernel(
    const __half* __restrict__ qkvhi, const __half* __restrict__ qkvlo,
    __half* __restrict__ oh)
{
    extern __shared__ __align__(16) char fsm[];
    const uint32_t fbase = smem_u32(fsm);

    const int tid  = threadIdx.x;
    const int lane = tid & 31;
    const int w    = tid >> 5;
    const int bh = blockIdx.y;
    const int b = bh >> 4, h = bh & 15;
    const int qrow0 = blockIdx.x * 128;

    const size_t hd_off = (size_t)b * Tk * D3k + h * HDk;

    float slope = 0.f;
#pragma unroll
    for (int i = 1; i <= Hk; i++) slope += exp2f(-0.5f * (float)i);
    slope *= (1.f / (float)Hk);
    const float scale = 0.125f;

    const int grow = tid >> 1;
    const int gcol = (tid & 1) * 32;
    const uint32_t gso = grow * (KST * 2) + gcol * 2;

    // ---- stage Q (hi/lo fp16) into stage-2 K slots
    {
        const uint32_t q_hi = fbase + 2 * STAGE_F;
        const uint32_t q_lo = q_hi + ARR_F;
        const __half* qh = qkvhi + hd_off + (size_t)(qrow0 + grow) * D3k + gcol;
        const __half* ql = qkvlo + hd_off + (size_t)(qrow0 + grow) * D3k + gcol;
#pragma unroll
        for (int j = 0; j < 4; j++) {
            sts128(q_hi + gso + j * 16, *(const uint4*)(qh + j * 8));
            sts128(q_lo + gso + j * 16, *(const uint4*)(ql + j * 8));
        }
    }
    __syncthreads();

    uint32_t Qh[4][4], Ql[4][4];
    {
        const uint32_t q_hi = fbase + 2 * STAGE_F;
        const uint32_t q_lo = q_hi + ARR_F;
        const uint32_t qOff = (w * 16 + (lane & 15)) * (KST * 2) + (lane >> 4) * 16;
#pragma unroll
        for (int kc = 0; kc < 4; kc++) {
            ldmat_x4(Qh[kc], q_hi + qOff + kc * 32);
            ldmat_x4(Ql[kc], q_lo + qOff + kc * 32);
        }
    }
    __syncthreads();   // Q reads done before stage-2 gets overwritten

    const __half* Khi_p = qkvhi + hd_off + Dk     + (size_t)grow * D3k + gcol;
    const __half* Klo_p = qkvlo + hd_off + Dk     + (size_t)grow * D3k + gcol;
    const __half* Vhi_p = qkvhi + hd_off + 2 * Dk + (size_t)grow * D3k + gcol;
    const __half* Vlo_p = qkvlo + hd_off + 2 * Dk + (size_t)grow * D3k + gcol;

    auto issueKV = [&](int kb, int s) {
        const uint32_t sb = fbase + s * STAGE_F;
        const size_t off = (size_t)(kb * 128) * D3k;
#pragma unroll
        for (int j = 0; j < 4; j++) {
            cp_async16(sb + gso + j * 16,               Khi_p + off + j * 8);
            cp_async16(sb + ARR_F + gso + j * 16,       Klo_p + off + j * 8);
            cp_async16(sb + 2 * ARR_F + gso + j * 16,   Vhi_p + off + j * 8);
            cp_async16(sb + 3 * ARR_F + gso + j * 16,   Vlo_p + off + j * 8);
        }
        CP_COMMIT();
    };

    const uint32_t bOff = (((lane >> 4) << 3) + (lane & 7)) * (KST * 2) + ((lane >> 3) & 1) * 16;
    const uint32_t vOff = ((lane & 7) + ((lane >> 3) & 1) * 8) * (KST * 2) + (lane >> 4) * 16;

    float Of[8][4];
#pragma unroll
    for (int i = 0; i < 8; i++)
#pragma unroll
        for (int q = 0; q < 4; q++) Of[i][q] = 0.f;
    float m0 = -1e30f, m1 = -1e30f, l0 = 0.f, l1 = 0.f;

    const float r0f = (float)(qrow0 + w * 16 + (lane >> 2));
    const float r1f = r0f + 8.f;

    constexpr int NKB = Tk / 128;   // 8
    issueKV(0, 0);
    issueKV(1, 1);

    for (int kb = 0; kb < NKB; kb++) {
        if (kb + 1 < NKB) { CP_WAIT1(); }
        else              { CP_WAIT0(); }
        __syncthreads();
        if (kb + 2 < NKB) issueKV(kb + 2, (kb + 2) % 3);

        const uint32_t sb  = fbase + (kb % 3) * STAGE_F;
        const uint32_t kHi = sb, kLo = sb + ARR_F, vHi = sb + 2 * ARR_F, vLo = sb + 3 * ARR_F;

        float Sf[16][4];
#pragma unroll
        for (int ntp = 0; ntp < 8; ntp++) {
#pragma unroll
            for (int q = 0; q < 4; q++) { Sf[2 * ntp][q] = 0.f; Sf[2 * ntp + 1][q] = 0.f; }
#pragma unroll
            for (int kc = 0; kc < 4; kc++) {
                uint32_t Bh4[4], Bl4[4];
                ldmat_x4(Bh4, kHi + bOff + ntp * (16 * KST * 2) + kc * 32);
                ldmat_x4(Bl4, kLo + bOff + ntp * (16 * KST * 2) + kc * 32);
                mma16816h(Sf[2 * ntp],     Qh[kc], Bh4[0], Bh4[1]);
                mma16816h(Sf[2 * ntp],     Qh[kc], Bl4[0], Bl4[1]);
                mma16816h(Sf[2 * ntp],     Ql[kc], Bh4[0], Bh4[1]);
                mma16816h(Sf[2 * ntp + 1], Qh[kc], Bh4[2], Bh4[3]);
                mma16816h(Sf[2 * ntp + 1], Qh[kc], Bl4[2], Bl4[3]);
                mma16816h(Sf[2 * ntp + 1], Ql[kc], Bh4[2], Bh4[3]);
            }
        }

        float bm0 = -1e30f, bm1 = -1e30f;
#pragma unroll
        for (int t = 0; t < 16; t++) {
            const float c0f = (float)(kb * 128 + t * 8 + (lane & 3) * 2);
            const float c1f = c0f + 1.f;
            Sf[t][0] = Sf[t][0] * scale - slope * fabsf(r0f - c0f);
            Sf[t][1] = Sf[t][1] * scale - slope * fabsf(r0f - c1f);
            Sf[t][2] = Sf[t][2] * scale - slope * fabsf(r1f - c0f);
            Sf[t][3] = Sf[t][3] * scale - slope * fabsf(r1f - c1f);
            bm0 = fmaxf(bm0, fmaxf(Sf[t][0], Sf[t][1]));
            bm1 = fmaxf(bm1, fmaxf(Sf[t][2], Sf[t][3]));
        }
        bm0 = fmaxf(bm0, __shfl_xor_sync(~0u, bm0, 1));
        bm0 = fmaxf(bm0, __shfl_xor_sync(~0u, bm0, 2));
        bm1 = fmaxf(bm1, __shfl_xor_sync(~0u, bm1, 1));
        bm1 = fmaxf(bm1, __shfl_xor_sync(~0u, bm1, 2));

        const float mn0 = fmaxf(m0, bm0), mn1 = fmaxf(m1, bm1);
        const float sc0 = __expf(m0 - mn0), sc1 = __expf(m1 - mn1);
        l0 *= sc0; l1 *= sc1;
#pragma unroll
        for (int nt = 0; nt < 8; nt++) {
            Of[nt][0] *= sc0; Of[nt][1] *= sc0;
            Of[nt][2] *= sc1; Of[nt][3] *= sc1;
        }
        m0 = mn0; m1 = mn1;

#pragma unroll
        for (int t = 0; t < 16; t++) {
            Sf[t][0] = __expf(Sf[t][0] - mn0);
            Sf[t][1] = __expf(Sf[t][1] - mn0);
            Sf[t][2] = __expf(Sf[t][2] - mn1);
            Sf[t][3] = __expf(Sf[t][3] - mn1);
            l0 += Sf[t][0] + Sf[t][1];
            l1 += Sf[t][2] + Sf[t][3];
        }

        uint32_t Ph[8][4], Pl[8][4];
#pragma unroll
        for (int kc = 0; kc < 8; kc++) {
            cvt_hilo2h(Sf[2 * kc][0],     Sf[2 * kc][1],     Ph[kc][0], Pl[kc][0]);
            cvt_hilo2h(Sf[2 * kc][2],     Sf[2 * kc][3],     Ph[kc][1], Pl[kc][1]);
            cvt_hilo2h(Sf[2 * kc + 1][0], Sf[2 * kc + 1][1], Ph[kc][2], Pl[kc][2]);
            cvt_hilo2h(Sf[2 * kc + 1][2], Sf[2 * kc + 1][3], Ph[kc][3], Pl[kc][3]);
        }

#pragma unroll
        for (int ntp = 0; ntp < 4; ntp++) {
#pragma unroll
            for (int kc = 0; kc < 8; kc++) {
                uint32_t Vh4[4], Vl4[4];
                ldmat_x4_t(Vh4, vHi + vOff + kc * (16 * KST * 2) + ntp * 32);
                ldmat_x4_t(Vl4, vLo + vOff + kc * (16 * KST * 2) + ntp * 32);
                mma16816h(Of[2 * ntp],     Ph[kc], Vh4[0], Vh4[1]);
                mma16816h(Of[2 * ntp],     Ph[kc], Vl4[0], Vl4[1]);
                mma16816h(Of[2 * ntp],     Pl[kc], Vh4[0], Vh4[1]);
                mma16816h(Of[2 * ntp + 1], Ph[kc], Vh4[2], Vh4[3]);
                mma16816h(Of[2 * ntp + 1], Ph[kc], Vl4[2], Vl4[3]);
                mma16816h(Of[2 * ntp + 1], Pl[kc], Vh4[2], Vh4[3]);
            }
        }
        __syncthreads();
    }

    l0 += __shfl_xor_sync(~0u, l0, 1);
    l0 += __shfl_xor_sync(~0u, l0, 2);
    l1 += __shfl_xor_sync(~0u, l1, 1);
    l1 += __shfl_xor_sync(~0u, l1, 2);
    const float inv0 = 1.f / l0, inv1 = 1.f / l1;

    const int row0 = qrow0 + w * 16 + (lane >> 2);
    __half* ohb = oh + (size_t)b * Tk * Dk + h * HDk;
#pragma unroll
    for (int nt = 0; nt < 8; nt++) {
        const int cc = nt * 8 + (lane & 3) * 2;
        *(uint32_t*)(ohb + (size_t)row0 * Dk + cc) =
            cvt_h2(Of[nt][0] * inv0, Of[nt][1] * inv0);
        *(uint32_t*)(ohb + (size_t)(row0 + 8) * Dk + cc) =
            cvt_h2(Of[nt][2] * inv1, Of[nt][3] * inv1);
    }
}

// ---------------------------------------------------------------------------
// h = LN(h + o) * g + b; also writes h as single fp16 for the next GEMM.
// ---------------------------------------------------------------------------
__global__ __launch_bounds__(256) void ln_residual_kernel(
    float* __restrict__ h, const float* __restrict__ o,
    const float* __restrict__ gam, const float* __restrict__ bet,
    __half* __restrict__ hh)
{
    __shared__ float rs[8], rs2[8];
    const size_t row = blockIdx.x;
    float* hp = h + row * Dk;
    const float* op = o + row * Dk;
    const int tid = threadIdx.x;

    float4 hv = ((const float4*)hp)[tid];
    float4 ov = ((const float4*)op)[tid];
    float r0 = hv.x + ov.x, r1 = hv.y + ov.y, r2 = hv.z + ov.z, r3 = hv.w + ov.w;

    float s  = r0 + r1 + r2 + r3;
    float s2 = r0 * r0 + r1 * r1 + r2 * r2 + r3 * r3;
#pragma unroll
    for (int of = 16; of; of >>= 1) {
        s  += __shfl_xor_sync(~0u, s,  of);
        s2 += __shfl_xor_sync(~0u, s2, of);
    }
    if ((tid & 31) == 0) { rs[tid >> 5] = s; rs2[tid >> 5] = s2; }
    __syncthreads();
    float S = 0.f, S2 = 0.f;
#pragma unroll
    for (int i = 0; i < 8; i++) { S += rs[i]; S2 += rs2[i]; }

    const float mu  = S * (1.f / (float)Dk);
    const float var = S2 * (1.f / (float)Dk) - mu * mu;
    const float inv = rsqrtf(var + EPSk);

    float4 gg = ((const float4*)gam)[tid];
    float4 bb = ((const float4*)bet)[tid];
    float4 out;
    out.x = (r0 - mu) * inv * gg.x + bb.x;
    out.y = (r1 - mu) * inv * gg.y + bb.y;
    out.z = (r2 - mu) * inv * gg.z + bb.z;
    out.w = (r3 - mu) * inv * gg.w + bb.w;
    ((float4*)hp)[tid] = out;

    *(uint2*)(hh + row * Dk + tid * 4) =
        make_uint2(cvt_h2(out.x, out.y), cvt_h2(out.z, out.w));
}

// ---------------------------------------------------------------------------
// head
// ---------------------------------------------------------------------------
__global__ void head_kernel(const float* __restrict__ h,
                            const float* __restrict__ hw,
                            const float* __restrict__ hb,
                            float* __restrict__ outp)
{
    const int idx = blockIdx.x;
    const int b = idx / Ck, c = idx % Ck;
    const float* hp = h + ((size_t)b * Tk + (Tk - 1)) * Dk;
    const float* wp = hw + (size_t)c * Dk;
    const int lane = threadIdx.x;
    float s = 0.f;
    for (int i = lane; i < Dk; i += 32) s += hp[i] * wp[i];
#pragma unroll
    for (int o = 16; o; o >>= 1) s += __shfl_xor_sync(~0u, s, o);
    if (lane == 0) outp[idx] = s + hb[c];
}

// ---------------------------------------------------------------------------
// Host orchestration
// ---------------------------------------------------------------------------
extern "C" void kernel_launch(void* const* d_in, const int* in_sizes, int n_in,
                              void* d_out, int out_size)
{
    (void)in_sizes; (void)n_in; (void)out_size;
    const float* x       = (const float*)d_in[0];
    const float* input_w = (const float*)d_in[1];
    const float* input_b = (const float*)d_in[2];
    const float* Wqkv    = (const float*)d_in[3];
    const float* bqkv    = (const float*)d_in[4];
    const float* Wo      = (const float*)d_in[5];
    const float* bo      = (const float*)d_in[6];
    const float* ln1_g   = (const float*)d_in[7];
    const float* ln1_b   = (const float*)d_in[8];
    const float* ln2_g   = (const float*)d_in[9];
    const float* ln2_b   = (const float*)d_in[10];
    const float* W1      = (const float*)d_in[11];
    const float* b1      = (const float*)d_in[12];
    const float* W2      = (const float*)d_in[13];
    const float* b2      = (const float*)d_in[14];
    const float* head_w  = (const float*)d_in[15];
    const float* head_b  = (const float*)d_in[16];
    float* outp = (float*)d_out;

    float *h, *tmp;
    __half *xh, *hh, *oh, *fh, *qhi, *qlo;
    __half *winh, *wqh, *woh, *w1h, *w2h;
    cudaGetSymbolAddress((void**)&h,    g_h);
    cudaGetSymbolAddress((void**)&tmp,  g_tmp);
    cudaGetSymbolAddress((void**)&xh,   g_x_h);
    cudaGetSymbolAddress((void**)&hh,   g_h_h);
    cudaGetSymbolAddress((void**)&oh,   g_o_h);
    cudaGetSymbolAddress((void**)&fh,   g_ff_h);
    cudaGetSymbolAddress((void**)&qhi,  g_qkv_hi); cudaGetSymbolAddress((void**)&qlo, g_qkv_lo);
    cudaGetSymbolAddress((void**)&winh, g_win_h);
    cudaGetSymbolAddress((void**)&wqh,  g_wqkv_h);
    cudaGetSymbolAddress((void**)&woh,  g_wo_h);
    cudaGetSymbolAddress((void**)&w1h,  g_w1_h);
    cudaGetSymbolAddress((void**)&w2h,  g_w2_h);

    cudaFuncSetAttribute(mma_gemm_f16_nt,
                         cudaFuncAttributeMaxDynamicSharedMemorySize, GEMM_SMEM);
    cudaFuncSetAttribute(flash_attn_kernel,
                         cudaFuncAttributeMaxDynamicSharedMemorySize, FLASH_SMEM);

    const int M = Bk * Tk;  // 4096
    dim3 blk(256);

    // ---- conversions: x, weights -> fp16
    cvt_h16_kernel<<<(Bk * Tk * INk) / 1024, 256>>>(x, xh, Bk * Tk * INk);
    cvt_h16_kernel<<<(Dk * INk) / 1024, 256>>>(input_w, winh, Dk * INk);
    cvt_h16_kernel<<<(Lk * D3k * Dk) / 1024, 256>>>(Wqkv, wqh, Lk * D3k * Dk);
    cvt_h16_kernel<<<(Lk * Dk * Dk) / 1024, 256>>>(Wo, woh, Lk * Dk * Dk);
    cvt_h16_kernel<<<(Lk * FFk * Dk) / 1024, 256>>>(W1, w1h, Lk * FFk * Dk);
    cvt_h16_kernel<<<(Lk * Dk * FFk) / 1024, 256>>>(W2, w2h, Lk * Dk * FFk);

    // ---- input projection: h (fp32) + h fp16
    mma_gemm_f16_nt<<<dim3(Dk / 128, M / 256), blk, GEMM_SMEM>>>(
        xh, INk, winh, INk, input_b, h, hh, nullptr, Dk, INk, 2 | 8);

    for (int l = 0; l < Lk; l++) {
        // qkv -> fp16 hi/lo (feeds 3-term flash)
        mma_gemm_f16_nt<<<dim3(D3k / 128, M / 256), blk, GEMM_SMEM>>>(
            hh, Dk, wqh + (size_t)l * D3k * Dk, Dk,
            bqkv + (size_t)l * D3k, nullptr, qhi, qlo, D3k, Dk, 4);
        // attention -> o fp16
        flash_attn_kernel<<<dim3(Tk / 128, Bk * Hk), blk, FLASH_SMEM>>>(qhi, qlo, oh);
        // Wo proj (fp32 out)
        mma_gemm_f16_nt<<<dim3(Dk / 128, M / 256), blk, GEMM_SMEM>>>(
            oh, Dk, woh + (size_t)l * Dk * Dk, Dk,
            bo + (size_t)l * Dk, tmp, nullptr, nullptr, Dk, Dk, 2);
        // LN1 -> h fp32 + h fp16
        ln_residual_kernel<<<M, 256>>>(h, tmp, ln1_g + (size_t)l * Dk, ln1_b + (size_t)l * Dk, hh);
        // FF1 (relu, fp16 out)
        mma_gemm_f16_nt<<<dim3(FFk / 128, M / 256), blk, GEMM_SMEM>>>(
            hh, Dk, w1h + (size_t)l * FFk * Dk, Dk,
            b1 + (size_t)l * FFk, nullptr, fh, nullptr, FFk, Dk, 1 | 8);
        // FF2 (fp32 out)
        mma_gemm_f16_nt<<<dim3(Dk / 128, M / 256), blk, GEMM_SMEM>>>(
            fh, FFk, w2h + (size_t)l * Dk * FFk, FFk,
            b2 + (size_t)l * Dk, tmp, nullptr, nullptr, Dk, FFk, 2);
        // LN2 -> h fp32 + h fp16
        ln_residual_kernel<<<M, 256>>>(h, tmp, ln2_g + (size_t)l * Dk, ln2_b + (size_t)l * Dk, hh);
    }

    head_kernel<<<Bk * Ck, 32>>>(h, head_w, head_b, outp);
}

// round 15
// speedup vs baseline: 1.2413x; 1.2413x over previous
#include <cuda_runtime.h>
#include <cuda_fp16.h>
#include <math.h>
#include <stdint.h>

// ---------------------------------------------------------------------------
// Problem constants
// ---------------------------------------------------------------------------
namespace {
constexpr int Bk = 4;       // batch
constexpr int Tk = 1024;    // seq len
constexpr int INk = 256;    // input dim
constexpr int Dk = 1024;    // model dim
constexpr int Hk = 16;      // heads
constexpr int HDk = 64;     // head dim
constexpr int FFk = 4096;   // ff dim
constexpr int Ck = 10;      // classes
constexpr int Lk = 6;       // layers
constexpr int D3k = 3 * Dk;
constexpr float EPSk = 1e-5f;
}

// ---------------------------------------------------------------------------
// Scratch buffers (static device globals — no allocations allowed)
// ---------------------------------------------------------------------------
__device__ float g_h[Bk * Tk * Dk];
__device__ float g_tmp[Bk * Tk * Dk];

// single fp16 activation buffers
__device__ __half g_x_h[Bk * Tk * INk];
__device__ __half g_h_h[Bk * Tk * Dk];
__device__ __half g_o_h[Bk * Tk * Dk];
__device__ __half g_ff_h[Bk * Tk * FFk];
// qkv kept hi/lo (QK consumes hi/lo; V consumes hi only)
__device__ __half g_qkv_hi[Bk * Tk * D3k], g_qkv_lo[Bk * Tk * D3k];

// fp16 weight buffers (single rounding)
__device__ __half g_win_h[Dk * INk];
__device__ __half g_wqkv_h[Lk * D3k * Dk];
__device__ __half g_wo_h[Lk * Dk * Dk];
__device__ __half g_w1_h[Lk * FFk * Dk];
__device__ __half g_w2_h[Lk * Dk * FFk];

// ---------------------------------------------------------------------------
// PTX helpers (sm_80-era features only — compile on base sm_100)
// ---------------------------------------------------------------------------
__device__ __forceinline__ uint32_t smem_u32(const void* p) {
    uint32_t a;
    asm("{ .reg .u64 t; cvta.to.shared.u64 t, %1; cvt.u32.u64 %0, t; }"
        : "=r"(a) : "l"(p));
    return a;
}

__device__ __forceinline__ void ldmat_x4(uint32_t* r, uint32_t addr) {
    asm volatile("ldmatrix.sync.aligned.m8n8.x4.shared.b16 {%0,%1,%2,%3}, [%4];"
                 : "=r"(r[0]), "=r"(r[1]), "=r"(r[2]), "=r"(r[3]) : "r"(addr));
}

__device__ __forceinline__ void ldmat_x4_t(uint32_t* r, uint32_t addr) {
    asm volatile("ldmatrix.sync.aligned.m8n8.x4.trans.shared.b16 {%0,%1,%2,%3}, [%4];"
                 : "=r"(r[0]), "=r"(r[1]), "=r"(r[2]), "=r"(r[3]) : "r"(addr));
}

// fp16 mma
__device__ __forceinline__ void mma16816h(float* c, const uint32_t* a,
                                          uint32_t b0, uint32_t b1) {
    asm volatile(
        "mma.sync.aligned.m16n8k16.row.col.f32.f16.f16.f32 "
        "{%0,%1,%2,%3}, {%4,%5,%6,%7}, {%8,%9}, {%0,%1,%2,%3};"
        : "+f"(c[0]), "+f"(c[1]), "+f"(c[2]), "+f"(c[3])
        : "r"(a[0]), "r"(a[1]), "r"(a[2]), "r"(a[3]), "r"(b0), "r"(b1));
}

__device__ __forceinline__ void sts128(uint32_t addr, uint4 v) {
    asm volatile("st.shared.v4.b32 [%0], {%1,%2,%3,%4};"
                 :: "r"(addr), "r"(v.x), "r"(v.y), "r"(v.z), "r"(v.w) : "memory");
}

__device__ __forceinline__ void cp_async16(uint32_t saddr, const void* gptr) {
    asm volatile("cp.async.cg.shared.global [%0], [%1], 16;"
                 :: "r"(saddr), "l"(gptr) : "memory");
}
#define CP_COMMIT() asm volatile("cp.async.commit_group;" ::: "memory")
#define CP_WAIT1()  asm volatile("cp.async.wait_group 1;" ::: "memory")
#define CP_WAIT0()  asm volatile("cp.async.wait_group 0;" ::: "memory")

// ---- fp16 hi/lo split
__device__ __forceinline__ void cvt_hilo2h(float a, float b, uint32_t& hi, uint32_t& lo) {
    __half2 h = __floats2half2_rn(a, b);
    float2 hf = __half22float2(h);
    __half2 l = __floats2half2_rn(a - hf.x, b - hf.y);
    hi = *reinterpret_cast<uint32_t*>(&h);
    lo = *reinterpret_cast<uint32_t*>(&l);
}

__device__ __forceinline__ uint32_t cvt_h2(float a, float b) {
    __half2 h = __floats2half2_rn(a, b);
    return *reinterpret_cast<uint32_t*>(&h);
}

// ---------------------------------------------------------------------------
// Conversion kernel (fp32 -> fp16)
// ---------------------------------------------------------------------------
__global__ __launch_bounds__(256) void cvt_h16_kernel(
    const float* __restrict__ src, __half* __restrict__ dst, int n)
{
    const int i = (blockIdx.x * 256 + threadIdx.x) * 4;
    if (i >= n) return;
    float4 v = *(const float4*)(src + i);
    *(uint2*)(dst + i) = make_uint2(cvt_h2(v.x, v.y), cvt_h2(v.z, v.w));
}

// ---------------------------------------------------------------------------
// fp16 single-term NT GEMM: C = A * W^T + bias.   (round-13 proven config)
// 128x128 tile, BK=32, 3-stage cp.async, 2 CTAs/SM.
// flags: 1=relu, 2=write fp32 C, 4=write fp16 hi/lo C, 8=write fp16 C
// ---------------------------------------------------------------------------
namespace {
constexpr int SST = 40;                        // smem row stride (fp16)
constexpr int ARR_B = 128 * SST * 2;           // 10240 bytes per tile array
constexpr int STAGE_B = 2 * ARR_B;             // A|B = 20480 bytes
}
static constexpr int GEMM_SMEM = 3 * STAGE_B;  // 61440

__global__ __launch_bounds__(256, 2) void mma_gemm_f16_nt(
    const __half* __restrict__ Ah, int lda,
    const __half* __restrict__ Bh, int ldb,
    const float* __restrict__ bias,
    float* __restrict__ Cf, __half* __restrict__ Chi, __half* __restrict__ Clo,
    int ldc, int K, int flags)
{
    extern __shared__ __align__(16) char gsm[];
    const uint32_t base = smem_u32(gsm);

    const int tid  = threadIdx.x;
    const int lane = tid & 31;
    const int wid  = tid >> 5;
    const int wm   = wid & 3;
    const int wn   = wid >> 2;
    const int row0 = blockIdx.y * 128;
    const int col0 = blockIdx.x * 128;

    const int grow = tid >> 1;
    const int gc16 = (tid & 1) * 16;
    const __half* Ah_p = Ah + (size_t)(row0 + grow) * lda + gc16;
    const __half* Bh_p = Bh + (size_t)(col0 + grow) * ldb + gc16;
    const uint32_t soff = grow * (SST * 2) + gc16 * 2;

    const uint32_t aRowOff = (uint32_t)((wm * 32 + (lane & 15)) * SST * 2 + (lane >> 4) * 16);
    const uint32_t bRowOff = (uint32_t)(((wn * 64 + ((lane >> 4) << 3) + (lane & 7)) * SST) * 2
                                        + ((lane >> 3) & 1) * 16);

    float acc[2][8][4];
#pragma unroll
    for (int i = 0; i < 2; i++)
#pragma unroll
        for (int j = 0; j < 8; j++)
#pragma unroll
            for (int q = 0; q < 4; q++) acc[i][j][q] = 0.f;

    const int nc = K >> 5;

    auto issue = [&](int c, int s) {
        const uint32_t sb = base + s * STAGE_B;
        const __half* p = Ah_p + c * 32;
        cp_async16(sb + soff, p);                 cp_async16(sb + soff + 16, p + 8);
        p = Bh_p + c * 32;
        cp_async16(sb + ARR_B + soff, p);         cp_async16(sb + ARR_B + soff + 16, p + 8);
        CP_COMMIT();
    };

    issue(0, 0);
    if (nc > 1) issue(1, 1);

    for (int c = 0; c < nc; c++) {
        if (c + 1 < nc) { CP_WAIT1(); }
        else            { CP_WAIT0(); }
        __syncthreads();
        if (c + 2 < nc) issue(c + 2, (c + 2) % 3);

        const uint32_t sb = base + (c % 3) * STAGE_B;
        const uint32_t aS = sb, bS = sb + ARR_B;

#pragma unroll
        for (int ks = 0; ks < 2; ks++) {
            const uint32_t kb = ks * 32;
            uint32_t A4[2][4];
#pragma unroll
            for (int mt = 0; mt < 2; mt++)
                ldmat_x4(A4[mt], aS + aRowOff + mt * (16 * SST * 2) + kb);
#pragma unroll
            for (int pr = 0; pr < 4; pr++) {
                uint32_t B4[4];
                ldmat_x4(B4, bS + bRowOff + pr * (16 * SST * 2) + kb);
#pragma unroll
                for (int sbb = 0; sbb < 2; sbb++) {
                    const int nt = pr * 2 + sbb;
#pragma unroll
                    for (int mt = 0; mt < 2; mt++)
                        mma16816h(acc[mt][nt], A4[mt], B4[sbb * 2], B4[sbb * 2 + 1]);
                }
            }
        }
    }
    __syncthreads();

    // ---- epilogue
    const int erow = lane >> 2;
    const int ecol = (lane & 3) * 2;
    const int relu = flags & 1;
#pragma unroll
    for (int mt = 0; mt < 2; mt++) {
        const int r = row0 + wm * 32 + mt * 16 + erow;
#pragma unroll
        for (int nt = 0; nt < 8; nt++) {
            const int cc = col0 + wn * 64 + nt * 8 + ecol;
            float2 bv = *(const float2*)(bias + cc);
            float2 v0, v1;
            v0.x = acc[mt][nt][0] + bv.x;  v0.y = acc[mt][nt][1] + bv.y;
            v1.x = acc[mt][nt][2] + bv.x;  v1.y = acc[mt][nt][3] + bv.y;
            if (relu) {
                v0.x = fmaxf(v0.x, 0.f); v0.y = fmaxf(v0.y, 0.f);
                v1.x = fmaxf(v1.x, 0.f); v1.y = fmaxf(v1.y, 0.f);
            }
            if (flags & 2) {
                *(float2*)(Cf + (size_t)r * ldc + cc)       = v0;
                *(float2*)(Cf + (size_t)(r + 8) * ldc + cc) = v1;
            }
            if (flags & 4) {
                uint32_t hv, lv;
                cvt_hilo2h(v0.x, v0.y, hv, lv);
                *(uint32_t*)(Chi + (size_t)r * ldc + cc) = hv;
                *(uint32_t*)(Clo + (size_t)r * ldc + cc) = lv;
                cvt_hilo2h(v1.x, v1.y, hv, lv);
                *(uint32_t*)(Chi + (size_t)(r + 8) * ldc + cc) = hv;
                *(uint32_t*)(Clo + (size_t)(r + 8) * ldc + cc) = lv;
            }
            if (flags & 8) {
                *(uint32_t*)(Chi + (size_t)r * ldc + cc)       = cvt_h2(v0.x, v0.y);
                *(uint32_t*)(Chi + (size_t)(r + 8) * ldc + cc) = cvt_h2(v1.x, v1.y);
            }
        }
    }
}

// ---------------------------------------------------------------------------
// Fused flash attention. QK: 3-term (Q,K hi/lo). PV: 2-term (V single fp16 —
// its lo term is destroyed by the fp16 output rounding anyway).
// K/V via cp.async 3-stage ring (Khi|Klo|Vh per stage). Output: fp16 o.
// ---------------------------------------------------------------------------
namespace {
constexpr int KST   = 72;                 // smem row stride (fp16)
constexpr int ARR_F = 128 * KST * 2;      // 18432 bytes per array
constexpr int STAGE_F = 3 * ARR_F;        // Khi|Klo|Vh = 55296
}
static constexpr int FLASH_SMEM = 3 * STAGE_F;   // 165888

__global__ __launch_bounds__(256) void flash_attn_kernel(
    const __half* __restrict__ qkvhi, const __half* __restrict__ qkvlo,
    __half* __restrict__ oh)
{
    extern __shared__ __align__(16) char fsm[];
    const uint32_t fbase = smem_u32(fsm);

    const int tid  = threadIdx.x;
    const int lane = tid & 31;
    const int w    = tid >> 5;
    const int bh = blockIdx.y;
    const int b = bh >> 4, h = bh & 15;
    const int qrow0 = blockIdx.x * 128;

    const size_t hd_off = (size_t)b * Tk * D3k + h * HDk;

    float slope = 0.f;
#pragma unroll
    for (int i = 1; i <= Hk; i++) slope += exp2f(-0.5f * (float)i);
    slope *= (1.f / (float)Hk);
    const float scale = 0.125f;

    const int grow = tid >> 1;
    const int gcol = (tid & 1) * 32;
    const uint32_t gso = grow * (KST * 2) + gcol * 2;

    // ---- stage Q (hi/lo fp16) into stage-2 slots
    {
        const uint32_t q_hi = fbase + 2 * STAGE_F;
        const uint32_t q_lo = q_hi + ARR_F;
        const __half* qh = qkvhi + hd_off + (size_t)(qrow0 + grow) * D3k + gcol;
        const __half* ql = qkvlo + hd_off + (size_t)(qrow0 + grow) * D3k + gcol;
#pragma unroll
        for (int j = 0; j < 4; j++) {
            sts128(q_hi + gso + j * 16, *(const uint4*)(qh + j * 8));
            sts128(q_lo + gso + j * 16, *(const uint4*)(ql + j * 8));
        }
    }
    __syncthreads();

    uint32_t Qh[4][4], Ql[4][4];
    {
        const uint32_t q_hi = fbase + 2 * STAGE_F;
        const uint32_t q_lo = q_hi + ARR_F;
        const uint32_t qOff = (w * 16 + (lane & 15)) * (KST * 2) + (lane >> 4) * 16;
#pragma unroll
        for (int kc = 0; kc < 4; kc++) {
            ldmat_x4(Qh[kc], q_hi + qOff + kc * 32);
            ldmat_x4(Ql[kc], q_lo + qOff + kc * 32);
        }
    }
    __syncthreads();   // Q reads done before stage-2 gets overwritten

    const __half* Khi_p = qkvhi + hd_off + Dk     + (size_t)grow * D3k + gcol;
    const __half* Klo_p = qkvlo + hd_off + Dk     + (size_t)grow * D3k + gcol;
    const __half* Vhi_p = qkvhi + hd_off + 2 * Dk + (size_t)grow * D3k + gcol;

    auto issueKV = [&](int kb, int s) {
        const uint32_t sb = fbase + s * STAGE_F;
        const size_t off = (size_t)(kb * 128) * D3k;
#pragma unroll
        for (int j = 0; j < 4; j++) {
            cp_async16(sb + gso + j * 16,               Khi_p + off + j * 8);
            cp_async16(sb + ARR_F + gso + j * 16,       Klo_p + off + j * 8);
            cp_async16(sb + 2 * ARR_F + gso + j * 16,   Vhi_p + off + j * 8);
        }
        CP_COMMIT();
    };

    const uint32_t bOff = (((lane >> 4) << 3) + (lane & 7)) * (KST * 2) + ((lane >> 3) & 1) * 16;
    const uint32_t vOff = ((lane & 7) + ((lane >> 3) & 1) * 8) * (KST * 2) + (lane >> 4) * 16;

    float Of[8][4];
#pragma unroll
    for (int i = 0; i < 8; i++)
#pragma unroll
        for (int q = 0; q < 4; q++) Of[i][q] = 0.f;
    float m0 = -1e30f, m1 = -1e30f, l0 = 0.f, l1 = 0.f;

    const float r0f = (float)(qrow0 + w * 16 + (lane >> 2));
    const float r1f = r0f + 8.f;

    constexpr int NKB = Tk / 128;   // 8
    issueKV(0, 0);
    issueKV(1, 1);

    for (int kb = 0; kb < NKB; kb++) {
        if (kb + 1 < NKB) { CP_WAIT1(); }
        else              { CP_WAIT0(); }
        __syncthreads();
        if (kb + 2 < NKB) issueKV(kb + 2, (kb + 2) % 3);

        const uint32_t sb  = fbase + (kb % 3) * STAGE_F;
        const uint32_t kHi = sb, kLo = sb + ARR_F, vHi = sb + 2 * ARR_F;

        // ---- S = Q K^T (3-term)
        float Sf[16][4];
#pragma unroll
        for (int ntp = 0; ntp < 8; ntp++) {
#pragma unroll
            for (int q = 0; q < 4; q++) { Sf[2 * ntp][q] = 0.f; Sf[2 * ntp + 1][q] = 0.f; }
#pragma unroll
            for (int kc = 0; kc < 4; kc++) {
                uint32_t Bh4[4], Bl4[4];
                ldmat_x4(Bh4, kHi + bOff + ntp * (16 * KST * 2) + kc * 32);
                ldmat_x4(Bl4, kLo + bOff + ntp * (16 * KST * 2) + kc * 32);
                mma16816h(Sf[2 * ntp],     Qh[kc], Bh4[0], Bh4[1]);
                mma16816h(Sf[2 * ntp],     Qh[kc], Bl4[0], Bl4[1]);
                mma16816h(Sf[2 * ntp],     Ql[kc], Bh4[0], Bh4[1]);
                mma16816h(Sf[2 * ntp + 1], Qh[kc], Bh4[2], Bh4[3]);
                mma16816h(Sf[2 * ntp + 1], Qh[kc], Bl4[2], Bl4[3]);
                mma16816h(Sf[2 * ntp + 1], Ql[kc], Bh4[2], Bh4[3]);
            }
        }

        // ---- scale + alibi + online softmax
        float bm0 = -1e30f, bm1 = -1e30f;
#pragma unroll
        for (int t = 0; t < 16; t++) {
            const float c0f = (float)(kb * 128 + t * 8 + (lane & 3) * 2);
            const float c1f = c0f + 1.f;
            Sf[t][0] = Sf[t][0] * scale - slope * fabsf(r0f - c0f);
            Sf[t][1] = Sf[t][1] * scale - slope * fabsf(r0f - c1f);
            Sf[t][2] = Sf[t][2] * scale - slope * fabsf(r1f - c0f);
            Sf[t][3] = Sf[t][3] * scale - slope * fabsf(r1f - c1f);
            bm0 = fmaxf(bm0, fmaxf(Sf[t][0], Sf[t][1]));
            bm1 = fmaxf(bm1, fmaxf(Sf[t][2], Sf[t][3]));
        }
        bm0 = fmaxf(bm0, __shfl_xor_sync(~0u, bm0, 1));
        bm0 = fmaxf(bm0, __shfl_xor_sync(~0u, bm0, 2));
        bm1 = fmaxf(bm1, __shfl_xor_sync(~0u, bm1, 1));
        bm1 = fmaxf(bm1, __shfl_xor_sync(~0u, bm1, 2));

        const float mn0 = fmaxf(m0, bm0), mn1 = fmaxf(m1, bm1);
        const float sc0 = __expf(m0 - mn0), sc1 = __expf(m1 - mn1);
        l0 *= sc0; l1 *= sc1;
#pragma unroll
        for (int nt = 0; nt < 8; nt++) {
            Of[nt][0] *= sc0; Of[nt][1] *= sc0;
            Of[nt][2] *= sc1; Of[nt][3] *= sc1;
        }
        m0 = mn0; m1 = mn1;

#pragma unroll
        for (int t = 0; t < 16; t++) {
            Sf[t][0] = __expf(Sf[t][0] - mn0);
            Sf[t][1] = __expf(Sf[t][1] - mn0);
            Sf[t][2] = __expf(Sf[t][2] - mn1);
            Sf[t][3] = __expf(Sf[t][3] - mn1);
            l0 += Sf[t][0] + Sf[t][1];
            l1 += Sf[t][2] + Sf[t][3];
        }

        // ---- P fragments (fp16 hi/lo)
        uint32_t Ph[8][4], Pl[8][4];
#pragma unroll
        for (int kc = 0; kc < 8; kc++) {
            cvt_hilo2h(Sf[2 * kc][0],     Sf[2 * kc][1],     Ph[kc][0], Pl[kc][0]);
            cvt_hilo2h(Sf[2 * kc][2],     Sf[2 * kc][3],     Ph[kc][1], Pl[kc][1]);
            cvt_hilo2h(Sf[2 * kc + 1][0], Sf[2 * kc + 1][1], Ph[kc][2], Pl[kc][2]);
            cvt_hilo2h(Sf[2 * kc + 1][2], Sf[2 * kc + 1][3], Ph[kc][3], Pl[kc][3]);
        }

        // ---- O += P V  (2-term: P hi/lo x V single)
#pragma unroll
        for (int ntp = 0; ntp < 4; ntp++) {
#pragma unroll
            for (int kc = 0; kc < 8; kc++) {
                uint32_t Vh4[4];
                ldmat_x4_t(Vh4, vHi + vOff + kc * (16 * KST * 2) + ntp * 32);
                mma16816h(Of[2 * ntp],     Ph[kc], Vh4[0], Vh4[1]);
                mma16816h(Of[2 * ntp],     Pl[kc], Vh4[0], Vh4[1]);
                mma16816h(Of[2 * ntp + 1], Ph[kc], Vh4[2], Vh4[3]);
                mma16816h(Of[2 * ntp + 1], Pl[kc], Vh4[2], Vh4[3]);
            }
        }
        __syncthreads();   // all reads of this stage done before re-issue
    }

    l0 += __shfl_xor_sync(~0u, l0, 1);
    l0 += __shfl_xor_sync(~0u, l0, 2);
    l1 += __shfl_xor_sync(~0u, l1, 1);
    l1 += __shfl_xor_sync(~0u, l1, 2);
    const float inv0 = 1.f / l0, inv1 = 1.f / l1;

    const int row0 = qrow0 + w * 16 + (lane >> 2);
    __half* ohb = oh + (size_t)b * Tk * Dk + h * HDk;
#pragma unroll
    for (int nt = 0; nt < 8; nt++) {
        const int cc = nt * 8 + (lane & 3) * 2;
        *(uint32_t*)(ohb + (size_t)row0 * Dk + cc) =
            cvt_h2(Of[nt][0] * inv0, Of[nt][1] * inv0);
        *(uint32_t*)(ohb + (size_t)(row0 + 8) * Dk + cc) =
            cvt_h2(Of[nt][2] * inv1, Of[nt][3] * inv1);
    }
}

// ---------------------------------------------------------------------------
// h = LN(h + o) * g + b; also writes h as single fp16 for the next GEMM.
// ---------------------------------------------------------------------------
__global__ __launch_bounds__(256) void ln_residual_kernel(
    float* __restrict__ h, const float* __restrict__ o,
    const float* __restrict__ gam, const float* __restrict__ bet,
    __half* __restrict__ hh)
{
    __shared__ float rs[8], rs2[8];
    const size_t row = blockIdx.x;
    float* hp = h + row * Dk;
    const float* op = o + row * Dk;
    const int tid = threadIdx.x;

    float4 hv = ((const float4*)hp)[tid];
    float4 ov = ((const float4*)op)[tid];
    float r0 = hv.x + ov.x, r1 = hv.y + ov.y, r2 = hv.z + ov.z, r3 = hv.w + ov.w;

    float s  = r0 + r1 + r2 + r3;
    float s2 = r0 * r0 + r1 * r1 + r2 * r2 + r3 * r3;
#pragma unroll
    for (int of = 16; of; of >>= 1) {
        s  += __shfl_xor_sync(~0u, s,  of);
        s2 += __shfl_xor_sync(~0u, s2, of);
    }
    if ((tid & 31) == 0) { rs[tid >> 5] = s; rs2[tid >> 5] = s2; }
    __syncthreads();
    float S = 0.f, S2 = 0.f;
#pragma unroll
    for (int i = 0; i < 8; i++) { S += rs[i]; S2 += rs2[i]; }

    const float mu  = S * (1.f / (float)Dk);
    const float var = S2 * (1.f / (float)Dk) - mu * mu;
    const float inv = rsqrtf(var + EPSk);

    float4 gg = ((const float4*)gam)[tid];
    float4 bb = ((const float4*)bet)[tid];
    float4 out;
    out.x = (r0 - mu) * inv * gg.x + bb.x;
    out.y = (r1 - mu) * inv * gg.y + bb.y;
    out.z = (r2 - mu) * inv * gg.z + bb.z;
    out.w = (r3 - mu) * inv * gg.w + bb.w;
    ((float4*)hp)[tid] = out;

    *(uint2*)(hh + row * Dk + tid * 4) =
        make_uint2(cvt_h2(out.x, out.y), cvt_h2(out.z, out.w));
}

// ---------------------------------------------------------------------------
// head
// ---------------------------------------------------------------------------
__global__ void head_kernel(const float* __restrict__ h,
                            const float* __restrict__ hw,
                            const float* __restrict__ hb,
                            float* __restrict__ outp)
{
    const int idx = blockIdx.x;
    const int b = idx / Ck, c = idx % Ck;
    const float* hp = h + ((size_t)b * Tk + (Tk - 1)) * Dk;
    const float* wp = hw + (size_t)c * Dk;
    const int lane = threadIdx.x;
    float s = 0.f;
    for (int i = lane; i < Dk; i += 32) s += hp[i] * wp[i];
#pragma unroll
    for (int o = 16; o; o >>= 1) s += __shfl_xor_sync(~0u, s, o);
    if (lane == 0) outp[idx] = s + hb[c];
}

// ---------------------------------------------------------------------------
// Host orchestration
// ---------------------------------------------------------------------------
extern "C" void kernel_launch(void* const* d_in, const int* in_sizes, int n_in,
                              void* d_out, int out_size)
{
    (void)in_sizes; (void)n_in; (void)out_size;
    const float* x       = (const float*)d_in[0];
    const float* input_w = (const float*)d_in[1];
    const float* input_b = (const float*)d_in[2];
    const float* Wqkv    = (const float*)d_in[3];
    const float* bqkv    = (const float*)d_in[4];
    const float* Wo      = (const float*)d_in[5];
    const float* bo      = (const float*)d_in[6];
    const float* ln1_g   = (const float*)d_in[7];
    const float* ln1_b   = (const float*)d_in[8];
    const float* ln2_g   = (const float*)d_in[9];
    const float* ln2_b   = (const float*)d_in[10];
    const float* W1      = (const float*)d_in[11];
    const float* b1      = (const float*)d_in[12];
    const float* W2      = (const float*)d_in[13];
    const float* b2      = (const float*)d_in[14];
    const float* head_w  = (const float*)d_in[15];
    const float* head_b  = (const float*)d_in[16];
    float* outp = (float*)d_out;

    float *h, *tmp;
    __half *xh, *hh, *oh, *fh, *qhi, *qlo;
    __half *winh, *wqh, *woh, *w1h, *w2h;
    cudaGetSymbolAddress((void**)&h,    g_h);
    cudaGetSymbolAddress((void**)&tmp,  g_tmp);
    cudaGetSymbolAddress((void**)&xh,   g_x_h);
    cudaGetSymbolAddress((void**)&hh,   g_h_h);
    cudaGetSymbolAddress((void**)&oh,   g_o_h);
    cudaGetSymbolAddress((void**)&fh,   g_ff_h);
    cudaGetSymbolAddress((void**)&qhi,  g_qkv_hi); cudaGetSymbolAddress((void**)&qlo, g_qkv_lo);
    cudaGetSymbolAddress((void**)&winh, g_win_h);
    cudaGetSymbolAddress((void**)&wqh,  g_wqkv_h);
    cudaGetSymbolAddress((void**)&woh,  g_wo_h);
    cudaGetSymbolAddress((void**)&w1h,  g_w1_h);
    cudaGetSymbolAddress((void**)&w2h,  g_w2_h);

    cudaFuncSetAttribute(mma_gemm_f16_nt,
                         cudaFuncAttributeMaxDynamicSharedMemorySize, GEMM_SMEM);
    cudaFuncSetAttribute(flash_attn_kernel,
                         cudaFuncAttributeMaxDynamicSharedMemorySize, FLASH_SMEM);

    const int M = Bk * Tk;  // 4096
    dim3 blk(256);

    // ---- conversions: x, weights -> fp16
    cvt_h16_kernel<<<(Bk * Tk * INk) / 1024, 256>>>(x, xh, Bk * Tk * INk);
    cvt_h16_kernel<<<(Dk * INk) / 1024, 256>>>(input_w, winh, Dk * INk);
    cvt_h16_kernel<<<(Lk * D3k * Dk) / 1024, 256>>>(Wqkv, wqh, Lk * D3k * Dk);
    cvt_h16_kernel<<<(Lk * Dk * Dk) / 1024, 256>>>(Wo, woh, Lk * Dk * Dk);
    cvt_h16_kernel<<<(Lk * FFk * Dk) / 1024, 256>>>(W1, w1h, Lk * FFk * Dk);
    cvt_h16_kernel<<<(Lk * Dk * FFk) / 1024, 256>>>(W2, w2h, Lk * Dk * FFk);

    // ---- input projection: h (fp32) + h fp16
    mma_gemm_f16_nt<<<dim3(Dk / 128, M / 128), blk, GEMM_SMEM>>>(
        xh, INk, winh, INk, input_b, h, hh, nullptr, Dk, INk, 2 | 8);

    for (int l = 0; l < Lk; l++) {
        // qkv -> fp16 hi/lo (QK 3-term; V uses hi only)
        mma_gemm_f16_nt<<<dim3(D3k / 128, M / 128), blk, GEMM_SMEM>>>(
            hh, Dk, wqh + (size_t)l * D3k * Dk, Dk,
            bqkv + (size_t)l * D3k, nullptr, qhi, qlo, D3k, Dk, 4);
        // attention -> o fp16
        flash_attn_kernel<<<dim3(Tk / 128, Bk * Hk), blk, FLASH_SMEM>>>(qhi, qlo, oh);
        // Wo proj (fp32 out)
        mma_gemm_f16_nt<<<dim3(Dk / 128, M / 128), blk, GEMM_SMEM>>>(
            oh, Dk, woh + (size_t)l * Dk * Dk, Dk,
            bo + (size_t)l * Dk, tmp, nullptr, nullptr, Dk, Dk, 2);
        // LN1 -> h fp32 + h fp16
        ln_residual_kernel<<<M, 256>>>(h, tmp, ln1_g + (size_t)l * Dk, ln1_b + (size_t)l * Dk, hh);
        // FF1 (relu, fp16 out)
        mma_gemm_f16_nt<<<dim3(FFk / 128, M / 128), blk, GEMM_SMEM>>>(
            hh, Dk, w1h + (size_t)l * FFk * Dk, Dk,
            b1 + (size_t)l * FFk, nullptr, fh, nullptr, FFk, Dk, 1 | 8);
        // FF2 (fp32 out)
        mma_gemm_f16_nt<<<dim3(Dk / 128, M / 128), blk, GEMM_SMEM>>>(
            fh, FFk, w2h + (size_t)l * Dk * FFk, FFk,
            b2 + (size_t)l * Dk, tmp, nullptr, nullptr, Dk, FFk, 2);
        // LN2 -> h fp32 + h fp16
        ln_residual_kernel<<<M, 256>>>(h, tmp, ln2_g + (size_t)l * Dk, ln2_b + (size_t)l * Dk, hh);
    }

    head_kernel<<<Bk * Ck, 32>>>(h, head_w, head_b, outp);
}